// round 15
// baseline (speedup 1.0000x reference)
#include <cuda_runtime.h>

// heightfield: [16,1,512,512] f32 -> same shape.
// out[w] = 1 - clip( max_{r=1..16}( pad(row)[w+r] - r/10 ) - row[w], 0, 1 )
// Hybrid shuffle kernel: each thread loads q0=[c0,c0+4) and q4=[c0+16,c0+20)
// (= lane l+4's q0). Middle quads' maxes come from 3 __shfl_down of the
// lane-local quad max M, bias-corrected by -0.4k. Lanes 29-31 load their
// missing quads directly. 4 outputs/thread, evict-first streaming stores.

#define IM 512
#define NEG (-1e30f)
#define THREADS 256

__global__ __launch_bounds__(THREADS) void shadow_hyb(const float* __restrict__ in,
                                                      float* __restrict__ out) {
    const int gtid = blockIdx.x * THREADS + threadIdx.x;
    const int c0 = gtid << 2;              // element index (row-major)
    const int col = c0 & (IM - 1);         // column within row
    const int lane = threadIdx.x & 31;

    const float* p = in + c0;

    // own quad, always in-row (col <= 508)
    float4 v0 = *reinterpret_cast<const float4*>(p);
    float g0 = v0.x;
    float g1 = v0.y - 0.1f;
    float g2 = v0.z - 0.2f;
    float g3 = v0.w - 0.3f;

    // q4 = [c0+16, c0+20), lane-local bias 1.6..1.9
    float q40, q41, q42, q43;
    if (col <= IM - 20) {
        float4 v4 = *reinterpret_cast<const float4*>(p + 16);
        q40 = v4.x - 1.6f; q41 = v4.y - 1.7f; q42 = v4.z - 1.8f; q43 = v4.w - 1.9f;
    } else {
        q40 = q41 = q42 = q43 = NEG;
    }

    // quad max (tree) of own quad
    const float M = fmaxf(fmaxf(g0, g1), fmaxf(g2, g3));

    // fallback local maxes for lanes whose l+k crosses the warp boundary
    float lm1 = NEG, lm2 = NEG, lm3 = NEG;
    if (lane >= 29) {
        #pragma unroll
        for (int k = 1; k <= 3; ++k) {
            float lm = NEG;
            if (col + 4 * k <= IM - 4) {
                float4 v = *reinterpret_cast<const float4*>(p + 4 * k);
                float a0 = v.x - 0.1f * (4 * k + 0);
                float a1 = v.y - 0.1f * (4 * k + 1);
                float a2 = v.z - 0.1f * (4 * k + 2);
                float a3 = v.w - 0.1f * (4 * k + 3);
                lm = fmaxf(fmaxf(a0, a1), fmaxf(a2, a3));
            }
            if (k == 1) lm1 = lm; else if (k == 2) lm2 = lm; else lm3 = lm;
        }
    }

    // neighbor quad maxes, bias-corrected into this lane's frame
    const unsigned FULL = 0xffffffffu;
    const float s1 = __shfl_down_sync(FULL, M, 1);
    const float s2 = __shfl_down_sync(FULL, M, 2);
    const float s3 = __shfl_down_sync(FULL, M, 3);
    const float M1 = (lane < 31) ? s1 - 0.4f : lm1;
    const float M2 = (lane < 30) ? s2 - 0.8f : lm2;
    const float M3 = (lane < 29) ? s3 - 1.2f : lm3;

    const float C = fmaxf(M1, fmaxf(M2, M3));   // cols c0+4 .. c0+15

    // suffixes of own quad, prefixes of q4
    const float S3 = g3;
    const float S2 = fmaxf(g2, g3);
    const float S1 = fmaxf(g1, S2);
    const float P0 = q40;
    const float P1 = fmaxf(P0, q41);
    const float P2 = fmaxf(P1, q42);
    const float P3 = fmaxf(P2, q43);

    // window j: cols [c0+j+1, c0+j+16]
    const float m0 = fmaxf(fmaxf(S1, C), P0);
    const float m1 = fmaxf(fmaxf(S2, C), P1);
    const float m2 = fmaxf(fmaxf(S3, C), P2);
    const float m3 = fmaxf(C, P3);

    float4 o;
    o.x = __saturatef(1.0f + (g0 - m0));
    o.y = __saturatef(1.0f + (g1 - m1));
    o.z = __saturatef(1.0f + (g2 - m2));
    o.w = __saturatef(1.0f + (g3 - m3));

    __stcs(reinterpret_cast<float4*>(out + c0), o);   // evict-first streaming store
}

extern "C" void kernel_launch(void* const* d_in, const int* in_sizes, int n_in,
                              void* d_out, int out_size) {
    const float* in = (const float*)d_in[0];
    float* out = (float*)d_out;
    const int n = in_sizes[0];                 // 4,194,304
    const int threads_total = n / 4;           // 1,048,576
    shadow_hyb<<<threads_total / THREADS, THREADS>>>(in, out);
}